// round 2
// baseline (speedup 1.0000x reference)
#include <cuda_runtime.h>
#include <math.h>

// Problem dims
#define BATCH 128
#define TSEQ  1024
#define DIN   128
#define HID   256
#define FOURH 1024
#define DOUT  1000
#define NCTA  128

// Scratch (device globals: allocation-free)
__device__ float d_xT[(size_t)TSEQ * DIN * BATCH];     // [t][k][b]  64 MB
__device__ float d_h1[2 * HID * BATCH];                // ping-pong, [parity][j][b]
__device__ float d_h2[2 * HID * BATCH];
__device__ unsigned g_arrive = 0;
__device__ unsigned g_release = 0;

typedef unsigned long long ull;

__device__ __forceinline__ ull pack2(float lo, float hi) {
    ull r;
    asm("mov.b64 %0, {%1, %2};" : "=l"(r) : "f"(lo), "f"(hi));
    return r;
}
__device__ __forceinline__ ull bcast2(float v) {
    ull r;
    asm("mov.b64 %0, {%1, %1};" : "=l"(r) : "f"(v));
    return r;
}
__device__ __forceinline__ void upk(ull v, float& lo, float& hi) {
    asm("mov.b64 {%0, %1}, %2;" : "=f"(lo), "=f"(hi) : "l"(v));
}
__device__ __forceinline__ void ffma2(ull& d, ull a, ull b) {
    asm("fma.rn.f32x2 %0, %1, %2, %0;" : "+l"(d) : "l"(a), "l"(b));
}
__device__ __forceinline__ float sigmoidf(float z) {
    return 1.0f / (1.0f + expf(-z));
}

// ---------------------------------------------------------------------------
// Kernel 1: transpose x [B][T][D] -> d_xT [T][D][B]
// ---------------------------------------------------------------------------
__global__ void transpose_x_kernel(const float* __restrict__ x) {
    __shared__ float tile[32][129];
    const int t  = blockIdx.x;
    const int b0 = blockIdx.y * 32;
    for (int idx = threadIdx.x; idx < 32 * 128; idx += 256) {
        int r = idx >> 7, k = idx & 127;
        tile[r][k] = x[(size_t)(b0 + r) * (TSEQ * DIN) + (size_t)t * DIN + k];
    }
    __syncthreads();
    for (int idx = threadIdx.x; idx < 32 * 128; idx += 256) {
        int k = idx >> 5, bb = idx & 31;
        d_xT[((size_t)t * DIN + k) * BATCH + b0 + bb] = tile[bb][k];
    }
}

// ---------------------------------------------------------------------------
// Kernel 2: zero the h state buffers
// ---------------------------------------------------------------------------
__global__ void init_state_kernel() {
    int i = blockIdx.x * blockDim.x + threadIdx.x;
    if (i < 2 * HID * BATCH) {
        d_h1[i] = 0.0f;
        d_h2[i] = 0.0f;
    }
}

// ---------------------------------------------------------------------------
// Kernel 3: persistent fused 2-layer LSTM recurrence.
// 128 CTAs; CTA owns hidden units {2*cta, 2*cta+1} of BOTH layers.
// Layer 2 runs one step behind layer 1 -> one grid barrier per iteration.
// Thread layout: tid = b (0..127) + 128*half;  half 0: k=[0,128), half 1: k=[128,256)
// half 1 additionally computes the x@W1 contribution (k over DIN=128).
// ---------------------------------------------------------------------------
__global__ void __launch_bounds__(256, 1)
lstm_persistent(const float* __restrict__ W1, const float* __restrict__ U1,
                const float* __restrict__ b1, const float* __restrict__ W2,
                const float* __restrict__ U2, const float* __restrict__ b2) {
    __shared__ __align__(16) ull sU1[256][4];
    __shared__ __align__(16) ull sW1[128][4];
    __shared__ __align__(16) ull sW2[256][4];
    __shared__ __align__(16) ull sU2[256][4];
    __shared__ __align__(16) ull red[16][128];

    const int tid  = threadIdx.x;
    const int b    = tid & 127;
    const int half = tid >> 7;
    const int u0   = 2 * blockIdx.x;

    // Pack weights into SMEM: column pairs -> 64-bit words.
    // local col c = u*4 + g  (u in {0,1}, gate order i,f,g,o); global col = g*HID + (u0+u)
    {
        int k = tid;  // exactly one k per thread (256 threads, 256 rows)
#pragma unroll
        for (int p = 0; p < 4; ++p) {
            int cA = 2 * p, cB = 2 * p + 1;
            int gcA = (cA & 3) * HID + u0 + (cA >> 2);
            int gcB = (cB & 3) * HID + u0 + (cB >> 2);
            sU1[k][p] = pack2(U1[k * FOURH + gcA], U1[k * FOURH + gcB]);
            sW2[k][p] = pack2(W2[k * FOURH + gcA], W2[k * FOURH + gcB]);
            sU2[k][p] = pack2(U2[k * FOURH + gcA], U2[k * FOURH + gcB]);
            if (k < 128)
                sW1[k][p] = pack2(W1[k * FOURH + gcA], W1[k * FOURH + gcB]);
        }
    }

    float B1g[8], B2g[8];
    if (!half) {
#pragma unroll
        for (int c = 0; c < 8; ++c) {
            int gc = (c & 3) * HID + u0 + (c >> 2);
            B1g[c] = b1[gc];
            B2g[c] = b2[gc];
        }
    }
    float c1s0 = 0.f, c1s1 = 0.f, c2s0 = 0.f, c2s1 = 0.f;

    unsigned my_gen = 0;
    if (tid == 0) my_gen = *(volatile unsigned*)&g_release;
    __syncthreads();

    for (int iter = 0; iter <= TSEQ; ++iter) {
        const int rp = iter & 1, wp = rp ^ 1;
        const float* __restrict__ h1r = d_h1 + rp * (HID * BATCH);
        const float* __restrict__ h2r = d_h2 + rp * (HID * BATCH);
        const int tx = (iter < TSEQ) ? iter : (TSEQ - 1);
        const float* __restrict__ xr = d_xT + (size_t)tx * (DIN * BATCH);

        ull a1[4] = {0, 0, 0, 0}, aW[4] = {0, 0, 0, 0};
        ull aU[4] = {0, 0, 0, 0}, aX[4] = {0, 0, 0, 0};
        const int k0 = half << 7;
        const float* hp1 = h1r + k0 * BATCH + b;
        const float* hp2 = h2r + k0 * BATCH + b;

        if (!half) {
#pragma unroll 4
            for (int k = 0; k < 128; ++k) {
                ull hb1 = bcast2(hp1[k * BATCH]);
                ull hb2 = bcast2(hp2[k * BATCH]);
                ulonglong2 wa = *(const ulonglong2*)&sU1[k][0];
                ulonglong2 wb = *(const ulonglong2*)&sU1[k][2];
                ffma2(a1[0], wa.x, hb1); ffma2(a1[1], wa.y, hb1);
                ffma2(a1[2], wb.x, hb1); ffma2(a1[3], wb.y, hb1);
                wa = *(const ulonglong2*)&sW2[k][0];
                wb = *(const ulonglong2*)&sW2[k][2];
                ffma2(aW[0], wa.x, hb1); ffma2(aW[1], wa.y, hb1);
                ffma2(aW[2], wb.x, hb1); ffma2(aW[3], wb.y, hb1);
                wa = *(const ulonglong2*)&sU2[k][0];
                wb = *(const ulonglong2*)&sU2[k][2];
                ffma2(aU[0], wa.x, hb2); ffma2(aU[1], wa.y, hb2);
                ffma2(aU[2], wb.x, hb2); ffma2(aU[3], wb.y, hb2);
            }
        } else {
#pragma unroll 4
            for (int k = 0; k < 128; ++k) {
                ull hb1 = bcast2(hp1[k * BATCH]);
                ull hb2 = bcast2(hp2[k * BATCH]);
                ull xb  = bcast2(xr[k * BATCH + b]);
                ulonglong2 wa = *(const ulonglong2*)&sU1[128 + k][0];
                ulonglong2 wb = *(const ulonglong2*)&sU1[128 + k][2];
                ffma2(a1[0], wa.x, hb1); ffma2(a1[1], wa.y, hb1);
                ffma2(a1[2], wb.x, hb1); ffma2(a1[3], wb.y, hb1);
                wa = *(const ulonglong2*)&sW2[128 + k][0];
                wb = *(const ulonglong2*)&sW2[128 + k][2];
                ffma2(aW[0], wa.x, hb1); ffma2(aW[1], wa.y, hb1);
                ffma2(aW[2], wb.x, hb1); ffma2(aW[3], wb.y, hb1);
                wa = *(const ulonglong2*)&sU2[128 + k][0];
                wb = *(const ulonglong2*)&sU2[128 + k][2];
                ffma2(aU[0], wa.x, hb2); ffma2(aU[1], wa.y, hb2);
                ffma2(aU[2], wb.x, hb2); ffma2(aU[3], wb.y, hb2);
                wa = *(const ulonglong2*)&sW1[k][0];
                wb = *(const ulonglong2*)&sW1[k][2];
                ffma2(aX[0], wa.x, xb); ffma2(aX[1], wa.y, xb);
                ffma2(aX[2], wb.x, xb); ffma2(aX[3], wb.y, xb);
            }
        }

        if (half) {
#pragma unroll
            for (int p = 0; p < 4; ++p) {
                red[p][b]      = a1[p];
                red[4 + p][b]  = aW[p];
                red[8 + p][b]  = aU[p];
                red[12 + p][b] = aX[p];
            }
        }
        __syncthreads();

        if (!half) {
            float z1[8], zW[8], zU[8];
#pragma unroll
            for (int p = 0; p < 4; ++p) {
                float lo, hi, l2, h2v, xlo, xhi;
                upk(a1[p], lo, hi);
                upk(red[p][b], l2, h2v);
                upk(red[12 + p][b], xlo, xhi);
                z1[2 * p]     = lo + l2 + xlo;
                z1[2 * p + 1] = hi + h2v + xhi;
                upk(aW[p], lo, hi);
                upk(red[4 + p][b], l2, h2v);
                zW[2 * p] = lo + l2; zW[2 * p + 1] = hi + h2v;
                upk(aU[p], lo, hi);
                upk(red[8 + p][b], l2, h2v);
                zU[2 * p] = lo + l2; zU[2 * p + 1] = hi + h2v;
            }
            if (iter < TSEQ) {
#pragma unroll
                for (int u = 0; u < 2; ++u) {
                    int cb = 4 * u;
                    float zi = z1[cb] + B1g[cb];
                    float zf = z1[cb + 1] + B1g[cb + 1];
                    float zg = z1[cb + 2] + B1g[cb + 2];
                    float zo = z1[cb + 3] + B1g[cb + 3];
                    float ig = sigmoidf(zi), fg = sigmoidf(zf);
                    float gv = fmaxf(zg, 0.f), og = sigmoidf(zo);
                    float c = (u == 0) ? c1s0 : c1s1;
                    c = fg * c + ig * gv;
                    if (u == 0) c1s0 = c; else c1s1 = c;
                    d_h1[wp * (HID * BATCH) + (u0 + u) * BATCH + b] = og * fmaxf(c, 0.f);
                }
            }
            if (iter >= 1) {
#pragma unroll
                for (int u = 0; u < 2; ++u) {
                    int cb = 4 * u;
                    float zi = zW[cb] + zU[cb] + B2g[cb];
                    float zf = zW[cb + 1] + zU[cb + 1] + B2g[cb + 1];
                    float zg = zW[cb + 2] + zU[cb + 2] + B2g[cb + 2];
                    float zo = zW[cb + 3] + zU[cb + 3] + B2g[cb + 3];
                    float ig = sigmoidf(zi), fg = sigmoidf(zf);
                    float gv = fmaxf(zg, 0.f), og = sigmoidf(zo);
                    float c = (u == 0) ? c2s0 : c2s1;
                    c = fg * c + ig * gv;
                    if (u == 0) c2s0 = c; else c2s1 = c;
                    d_h2[wp * (HID * BATCH) + (u0 + u) * BATCH + b] = og * fmaxf(c, 0.f);
                }
            }
        }

        __threadfence();
        __syncthreads();
        if (tid == 0) {
            unsigned a = atomicAdd(&g_arrive, 1u);
            if (a == NCTA - 1) {
                atomicExch(&g_arrive, 0u);
                __threadfence();
                atomicAdd(&g_release, 1u);
            } else {
                unsigned tgt = my_gen + (unsigned)iter + 1u;
                while ((int)(*(volatile unsigned*)&g_release - tgt) < 0) {}
            }
            __threadfence();
        }
        __syncthreads();
    }
}

// ---------------------------------------------------------------------------
// Kernel 4: dense + softmax.  h_last lives in d_h2 parity 1 (iter 1024 wrote wp=1).
// One CTA per batch row.
// ---------------------------------------------------------------------------
__global__ void __launch_bounds__(256, 1)
dense_softmax_kernel(const float* __restrict__ Wd, const float* __restrict__ bd,
                     float* __restrict__ out) {
    const int b = blockIdx.x;
    const int tid = threadIdx.x;
    __shared__ float sh[HID];
    __shared__ float lg[DOUT];
    __shared__ float rbuf[8];

    sh[tid] = d_h2[1 * (HID * BATCH) + tid * BATCH + b];
    __syncthreads();

    float lmax = -1e30f;
    for (int o = tid; o < DOUT; o += 256) {
        float a = bd[o];
#pragma unroll 4
        for (int k = 0; k < HID; ++k) a += sh[k] * Wd[k * DOUT + o];
        lg[o] = a;
        lmax = fmaxf(lmax, a);
    }
#pragma unroll
    for (int off = 16; off; off >>= 1)
        lmax = fmaxf(lmax, __shfl_xor_sync(0xffffffffu, lmax, off));
    if ((tid & 31) == 0) rbuf[tid >> 5] = lmax;
    __syncthreads();
    if (tid == 0) {
        float m = rbuf[0];
#pragma unroll
        for (int i = 1; i < 8; ++i) m = fmaxf(m, rbuf[i]);
        rbuf[0] = m;
    }
    __syncthreads();
    const float M = rbuf[0];
    __syncthreads();

    float lsum = 0.f;
    for (int o = tid; o < DOUT; o += 256) {
        float e = expf(lg[o] - M);
        lg[o] = e;
        lsum += e;
    }
#pragma unroll
    for (int off = 16; off; off >>= 1)
        lsum += __shfl_xor_sync(0xffffffffu, lsum, off);
    if ((tid & 31) == 0) rbuf[tid >> 5] = lsum;
    __syncthreads();
    if (tid == 0) {
        float s = 0.f;
#pragma unroll
        for (int i = 0; i < 8; ++i) s += rbuf[i];
        rbuf[0] = s;
    }
    __syncthreads();
    const float inv = 1.0f / rbuf[0];
    for (int o = tid; o < DOUT; o += 256)
        out[(size_t)b * DOUT + o] = lg[o] * inv;
}

// ---------------------------------------------------------------------------
extern "C" void kernel_launch(void* const* d_in, const int* in_sizes, int n_in,
                              void* d_out, int out_size) {
    const float* x  = (const float*)d_in[0];
    const float* W1 = (const float*)d_in[1];
    const float* U1 = (const float*)d_in[2];
    const float* b1 = (const float*)d_in[3];
    const float* W2 = (const float*)d_in[4];
    const float* U2 = (const float*)d_in[5];
    const float* b2 = (const float*)d_in[6];
    const float* Wd = (const float*)d_in[7];
    const float* bd = (const float*)d_in[8];
    float* out = (float*)d_out;

    transpose_x_kernel<<<dim3(TSEQ, 4), 256>>>(x);
    init_state_kernel<<<(2 * HID * BATCH + 255) / 256, 256>>>();
    lstm_persistent<<<NCTA, 256>>>(W1, U1, b1, W2, U2, b2);
    dense_softmax_kernel<<<BATCH, 256>>>(Wd, bd, out);
}

// round 3
// speedup vs baseline: 1.0559x; 1.0559x over previous
#include <cuda_runtime.h>
#include <math.h>

// Problem dims
#define BATCH 128
#define TSEQ  1024
#define DIN   128
#define HID   256
#define FOURH 1024
#define DOUT  1000
#define NCTA  128

// Scratch (device globals: allocation-free)
__device__ float d_xT[(size_t)TSEQ * DIN * BATCH];     // [t][k][b]  64 MB
__device__ float d_h1[2 * HID * BATCH];                // ping-pong, [parity][j][b]
__device__ float d_h2[2 * HID * BATCH];
__device__ int   g_flags[NCTA];

typedef unsigned long long ull;

__device__ __forceinline__ ull pack2(float lo, float hi) {
    ull r;
    asm("mov.b64 %0, {%1, %2};" : "=l"(r) : "f"(lo), "f"(hi));
    return r;
}
__device__ __forceinline__ ull bcast2(float v) {
    ull r;
    asm("mov.b64 %0, {%1, %1};" : "=l"(r) : "f"(v));
    return r;
}
__device__ __forceinline__ void upk(ull v, float& lo, float& hi) {
    asm("mov.b64 {%0, %1}, %2;" : "=f"(lo), "=f"(hi) : "l"(v));
}
__device__ __forceinline__ void ffma2(ull& d, ull a, ull b) {
    asm("fma.rn.f32x2 %0, %1, %2, %0;" : "+l"(d) : "l"(a), "l"(b));
}
__device__ __forceinline__ float sigmoidf(float z) {
    return __fdividef(1.0f, 1.0f + __expf(-z));
}

// ---------------------------------------------------------------------------
// Kernel 1: transpose x [B][T][D] -> d_xT [T][D][B]
// ---------------------------------------------------------------------------
__global__ void transpose_x_kernel(const float* __restrict__ x) {
    __shared__ float tile[32][129];
    const int t  = blockIdx.x;
    const int b0 = blockIdx.y * 32;
    for (int idx = threadIdx.x; idx < 32 * 128; idx += 256) {
        int r = idx >> 7, k = idx & 127;
        tile[r][k] = x[(size_t)(b0 + r) * (TSEQ * DIN) + (size_t)t * DIN + k];
    }
    __syncthreads();
    for (int idx = threadIdx.x; idx < 32 * 128; idx += 256) {
        int k = idx >> 5, bb = idx & 31;
        d_xT[((size_t)t * DIN + k) * BATCH + b0 + bb] = tile[bb][k];
    }
}

// ---------------------------------------------------------------------------
// Kernel 2: zero state + barrier flags (runs each graph replay -> deterministic)
// ---------------------------------------------------------------------------
__global__ void init_state_kernel() {
    int i = blockIdx.x * blockDim.x + threadIdx.x;
    if (i < 2 * HID * BATCH) {
        d_h1[i] = 0.0f;
        d_h2[i] = 0.0f;
    }
    if (i < NCTA) g_flags[i] = 0;
}

// ---------------------------------------------------------------------------
// Inner dot-product phase: 128 k-steps, software pipelined (2 reg buffers of 4).
// WX=1 additionally accumulates the x@W1 stream.
// All h / x loads are .cg (L2-coherent, no L1 staleness, no fences needed).
// ---------------------------------------------------------------------------
template<int WX>
__device__ __forceinline__ void dot128(
    const float* __restrict__ hp1, const float* __restrict__ hp2,
    const float* __restrict__ xp,
    const ull (* __restrict__ wU1)[4], const ull (* __restrict__ wW2)[4],
    const ull (* __restrict__ wU2)[4], const ull (* __restrict__ wW1)[4],
    ull (&a1)[4], ull (&aW)[4], ull (&aU)[4], ull (&aX)[4])
{
    float A1[4], A2[4], A3[4], B1[4], B2[4], B3[4];
#pragma unroll
    for (int j = 0; j < 4; ++j) {
        A1[j] = __ldcg(hp1 + j * BATCH);
        A2[j] = __ldcg(hp2 + j * BATCH);
        if (WX) A3[j] = __ldcg(xp + j * BATCH);
    }
    for (int i = 0; i < 16; ++i) {
        const int kb = i * 8;
        // prefetch buffer B: k = kb+4 .. kb+7
#pragma unroll
        for (int j = 0; j < 4; ++j) {
            B1[j] = __ldcg(hp1 + (kb + 4 + j) * BATCH);
            B2[j] = __ldcg(hp2 + (kb + 4 + j) * BATCH);
            if (WX) B3[j] = __ldcg(xp + (kb + 4 + j) * BATCH);
        }
        // compute on A: k = kb .. kb+3
#pragma unroll
        for (int j = 0; j < 4; ++j) {
            const int k = kb + j;
            ull hb1 = bcast2(A1[j]);
            ull hb2 = bcast2(A2[j]);
            ulonglong2 wa = *(const ulonglong2*)&wU1[k][0];
            ulonglong2 wb = *(const ulonglong2*)&wU1[k][2];
            ffma2(a1[0], wa.x, hb1); ffma2(a1[1], wa.y, hb1);
            ffma2(a1[2], wb.x, hb1); ffma2(a1[3], wb.y, hb1);
            wa = *(const ulonglong2*)&wW2[k][0];
            wb = *(const ulonglong2*)&wW2[k][2];
            ffma2(aW[0], wa.x, hb1); ffma2(aW[1], wa.y, hb1);
            ffma2(aW[2], wb.x, hb1); ffma2(aW[3], wb.y, hb1);
            wa = *(const ulonglong2*)&wU2[k][0];
            wb = *(const ulonglong2*)&wU2[k][2];
            ffma2(aU[0], wa.x, hb2); ffma2(aU[1], wa.y, hb2);
            ffma2(aU[2], wb.x, hb2); ffma2(aU[3], wb.y, hb2);
            if (WX) {
                ull xb = bcast2(A3[j]);
                wa = *(const ulonglong2*)&wW1[k][0];
                wb = *(const ulonglong2*)&wW1[k][2];
                ffma2(aX[0], wa.x, xb); ffma2(aX[1], wa.y, xb);
                ffma2(aX[2], wb.x, xb); ffma2(aX[3], wb.y, xb);
            }
        }
        // prefetch buffer A for next iter: k = kb+8 .. kb+11 (clamped, stays in-bounds)
        const int kn = (i < 15) ? (kb + 8) : 120;
#pragma unroll
        for (int j = 0; j < 4; ++j) {
            A1[j] = __ldcg(hp1 + (kn + j) * BATCH);
            A2[j] = __ldcg(hp2 + (kn + j) * BATCH);
            if (WX) A3[j] = __ldcg(xp + (kn + j) * BATCH);
        }
        // compute on B: k = kb+4 .. kb+7
#pragma unroll
        for (int j = 0; j < 4; ++j) {
            const int k = kb + 4 + j;
            ull hb1 = bcast2(B1[j]);
            ull hb2 = bcast2(B2[j]);
            ulonglong2 wa = *(const ulonglong2*)&wU1[k][0];
            ulonglong2 wb = *(const ulonglong2*)&wU1[k][2];
            ffma2(a1[0], wa.x, hb1); ffma2(a1[1], wa.y, hb1);
            ffma2(a1[2], wb.x, hb1); ffma2(a1[3], wb.y, hb1);
            wa = *(const ulonglong2*)&wW2[k][0];
            wb = *(const ulonglong2*)&wW2[k][2];
            ffma2(aW[0], wa.x, hb1); ffma2(aW[1], wa.y, hb1);
            ffma2(aW[2], wb.x, hb1); ffma2(aW[3], wb.y, hb1);
            wa = *(const ulonglong2*)&wU2[k][0];
            wb = *(const ulonglong2*)&wU2[k][2];
            ffma2(aU[0], wa.x, hb2); ffma2(aU[1], wa.y, hb2);
            ffma2(aU[2], wb.x, hb2); ffma2(aU[3], wb.y, hb2);
            if (WX) {
                ull xb = bcast2(B3[j]);
                wa = *(const ulonglong2*)&wW1[k][0];
                wb = *(const ulonglong2*)&wW1[k][2];
                ffma2(aX[0], wa.x, xb); ffma2(aX[1], wa.y, xb);
                ffma2(aX[2], wb.x, xb); ffma2(aX[3], wb.y, xb);
            }
        }
    }
}

// ---------------------------------------------------------------------------
// Kernel 3: persistent fused 2-layer LSTM recurrence.
// 128 CTAs; CTA owns hidden units {2*cta, 2*cta+1} of BOTH layers.
// Layer 2 runs one step behind layer 1 -> one grid barrier per iteration.
// Barrier = per-CTA flag (st.release.gpu) + warp-0 poll (ld.acquire.gpu).
// ---------------------------------------------------------------------------
__global__ void __launch_bounds__(256, 1)
lstm_persistent(const float* __restrict__ W1, const float* __restrict__ U1,
                const float* __restrict__ b1, const float* __restrict__ W2,
                const float* __restrict__ U2, const float* __restrict__ b2) {
    __shared__ __align__(16) ull sU1[256][4];
    __shared__ __align__(16) ull sW1[128][4];
    __shared__ __align__(16) ull sW2[256][4];
    __shared__ __align__(16) ull sU2[256][4];
    __shared__ __align__(16) ull red[16][128];

    const int tid  = threadIdx.x;
    const int b    = tid & 127;
    const int half = tid >> 7;
    const int u0   = 2 * blockIdx.x;

    // Pack weights into SMEM: column pairs -> 64-bit words.
    // local col c = u*4 + g  (u in {0,1}, gate order i,f,g,o); global col = g*HID + (u0+u)
    {
        int k = tid;  // one k-row per thread (256 threads, 256 rows)
#pragma unroll
        for (int p = 0; p < 4; ++p) {
            int cA = 2 * p, cB = 2 * p + 1;
            int gcA = (cA & 3) * HID + u0 + (cA >> 2);
            int gcB = (cB & 3) * HID + u0 + (cB >> 2);
            sU1[k][p] = pack2(U1[k * FOURH + gcA], U1[k * FOURH + gcB]);
            sW2[k][p] = pack2(W2[k * FOURH + gcA], W2[k * FOURH + gcB]);
            sU2[k][p] = pack2(U2[k * FOURH + gcA], U2[k * FOURH + gcB]);
            if (k < 128)
                sW1[k][p] = pack2(W1[k * FOURH + gcA], W1[k * FOURH + gcB]);
        }
    }

    float B1g[8], B2g[8];
    if (!half) {
#pragma unroll
        for (int c = 0; c < 8; ++c) {
            int gc = (c & 3) * HID + u0 + (c >> 2);
            B1g[c] = b1[gc];
            B2g[c] = b2[gc];
        }
    }
    float c1s0 = 0.f, c1s1 = 0.f, c2s0 = 0.f, c2s1 = 0.f;
    __syncthreads();

    for (int iter = 0; iter <= TSEQ; ++iter) {
        const int rp = iter & 1, wp = rp ^ 1;
        const float* __restrict__ h1r = d_h1 + rp * (HID * BATCH);
        const float* __restrict__ h2r = d_h2 + rp * (HID * BATCH);
        const int tx = (iter < TSEQ) ? iter : (TSEQ - 1);
        const float* __restrict__ xr = d_xT + (size_t)tx * (DIN * BATCH);

        ull a1[4] = {0, 0, 0, 0}, aW[4] = {0, 0, 0, 0};
        ull aU[4] = {0, 0, 0, 0}, aX[4] = {0, 0, 0, 0};

        if (!half) {
            dot128<0>(h1r + b, h2r + b, nullptr,
                      sU1, sW2, sU2, nullptr, a1, aW, aU, aX);
        } else {
            dot128<1>(h1r + 128 * BATCH + b, h2r + 128 * BATCH + b, xr + b,
                      sU1 + 128, sW2 + 128, sU2 + 128, sW1, a1, aW, aU, aX);
        }

        if (half) {
#pragma unroll
            for (int p = 0; p < 4; ++p) {
                red[p][b]      = a1[p];
                red[4 + p][b]  = aW[p];
                red[8 + p][b]  = aU[p];
                red[12 + p][b] = aX[p];
            }
        }
        __syncthreads();

        if (!half) {
            float z1[8], zW[8], zU[8];
#pragma unroll
            for (int p = 0; p < 4; ++p) {
                float lo, hi, l2, h2v, xlo, xhi;
                upk(a1[p], lo, hi);
                upk(red[p][b], l2, h2v);
                upk(red[12 + p][b], xlo, xhi);
                z1[2 * p]     = lo + l2 + xlo;
                z1[2 * p + 1] = hi + h2v + xhi;
                upk(aW[p], lo, hi);
                upk(red[4 + p][b], l2, h2v);
                zW[2 * p] = lo + l2; zW[2 * p + 1] = hi + h2v;
                upk(aU[p], lo, hi);
                upk(red[8 + p][b], l2, h2v);
                zU[2 * p] = lo + l2; zU[2 * p + 1] = hi + h2v;
            }
            if (iter < TSEQ) {
#pragma unroll
                for (int u = 0; u < 2; ++u) {
                    int cb = 4 * u;
                    float zi = z1[cb] + B1g[cb];
                    float zf = z1[cb + 1] + B1g[cb + 1];
                    float zg = z1[cb + 2] + B1g[cb + 2];
                    float zo = z1[cb + 3] + B1g[cb + 3];
                    float ig = sigmoidf(zi), fg = sigmoidf(zf);
                    float gv = fmaxf(zg, 0.f), og = sigmoidf(zo);
                    float c = (u == 0) ? c1s0 : c1s1;
                    c = fg * c + ig * gv;
                    if (u == 0) c1s0 = c; else c1s1 = c;
                    __stcg(&d_h1[wp * (HID * BATCH) + (u0 + u) * BATCH + b],
                           og * fmaxf(c, 0.f));
                }
            }
            if (iter >= 1) {
#pragma unroll
                for (int u = 0; u < 2; ++u) {
                    int cb = 4 * u;
                    float zi = zW[cb] + zU[cb] + B2g[cb];
                    float zf = zW[cb + 1] + zU[cb + 1] + B2g[cb + 1];
                    float zg = zW[cb + 2] + zU[cb + 2] + B2g[cb + 2];
                    float zo = zW[cb + 3] + zU[cb + 3] + B2g[cb + 3];
                    float ig = sigmoidf(zi), fg = sigmoidf(zf);
                    float gv = fmaxf(zg, 0.f), og = sigmoidf(zo);
                    float c = (u == 0) ? c2s0 : c2s1;
                    c = fg * c + ig * gv;
                    if (u == 0) c2s0 = c; else c2s1 = c;
                    __stcg(&d_h2[wp * (HID * BATCH) + (u0 + u) * BATCH + b],
                           og * fmaxf(c, 0.f));
                }
            }
        }

        if (iter < TSEQ) {
            __syncthreads();      // all CTA stores for this step issued
            if (tid == 0) {
                // release: cumulative -> covers all threads' prior .cg stores
                asm volatile("st.release.gpu.global.s32 [%0], %1;"
                             :: "l"(g_flags + blockIdx.x), "r"(iter + 1) : "memory");
            }
            if (tid < 32) {
                const int tgt = iter + 1;
                int ok;
                do {
                    ok = 1;
#pragma unroll
                    for (int s = 0; s < NCTA / 32; ++s) {
                        int v;
                        asm volatile("ld.acquire.gpu.global.s32 %0, [%1];"
                                     : "=r"(v) : "l"(g_flags + s * 32 + tid));
                        ok &= (v >= tgt);
                    }
                } while (!__all_sync(0xffffffffu, ok));
            }
            __syncthreads();      // whole CTA released
        }
    }
}

// ---------------------------------------------------------------------------
// Kernel 4: dense + softmax.  h_last lives in d_h2 parity 1 (iter 1024 wrote wp=1).
// One CTA per batch row.
// ---------------------------------------------------------------------------
__global__ void __launch_bounds__(256, 1)
dense_softmax_kernel(const float* __restrict__ Wd, const float* __restrict__ bd,
                     float* __restrict__ out) {
    const int b = blockIdx.x;
    const int tid = threadIdx.x;
    __shared__ float sh[HID];
    __shared__ float lg[DOUT];
    __shared__ float rbuf[8];

    sh[tid] = d_h2[1 * (HID * BATCH) + tid * BATCH + b];
    __syncthreads();

    float lmax = -1e30f;
    for (int o = tid; o < DOUT; o += 256) {
        float a = bd[o];
#pragma unroll 8
        for (int k = 0; k < HID; ++k) a += sh[k] * Wd[k * DOUT + o];
        lg[o] = a;
        lmax = fmaxf(lmax, a);
    }
#pragma unroll
    for (int off = 16; off; off >>= 1)
        lmax = fmaxf(lmax, __shfl_xor_sync(0xffffffffu, lmax, off));
    if ((tid & 31) == 0) rbuf[tid >> 5] = lmax;
    __syncthreads();
    if (tid == 0) {
        float m = rbuf[0];
#pragma unroll
        for (int i = 1; i < 8; ++i) m = fmaxf(m, rbuf[i]);
        rbuf[0] = m;
    }
    __syncthreads();
    const float M = rbuf[0];
    __syncthreads();

    float lsum = 0.f;
    for (int o = tid; o < DOUT; o += 256) {
        float e = __expf(lg[o] - M);
        lg[o] = e;
        lsum += e;
    }
#pragma unroll
    for (int off = 16; off; off >>= 1)
        lsum += __shfl_xor_sync(0xffffffffu, lsum, off);
    if ((tid & 31) == 0) rbuf[tid >> 5] = lsum;
    __syncthreads();
    if (tid == 0) {
        float s = 0.f;
#pragma unroll
        for (int i = 0; i < 8; ++i) s += rbuf[i];
        rbuf[0] = s;
    }
    __syncthreads();
    const float inv = 1.0f / rbuf[0];
    for (int o = tid; o < DOUT; o += 256)
        out[(size_t)b * DOUT + o] = lg[o] * inv;
}

// ---------------------------------------------------------------------------
extern "C" void kernel_launch(void* const* d_in, const int* in_sizes, int n_in,
                              void* d_out, int out_size) {
    const float* x  = (const float*)d_in[0];
    const float* W1 = (const float*)d_in[1];
    const float* U1 = (const float*)d_in[2];
    const float* b1 = (const float*)d_in[3];
    const float* W2 = (const float*)d_in[4];
    const float* U2 = (const float*)d_in[5];
    const float* b2 = (const float*)d_in[6];
    const float* Wd = (const float*)d_in[7];
    const float* bd = (const float*)d_in[8];
    float* out = (float*)d_out;

    transpose_x_kernel<<<dim3(TSEQ, 4), 256>>>(x);
    init_state_kernel<<<(2 * HID * BATCH + 255) / 256, 256>>>();
    lstm_persistent<<<NCTA, 256>>>(W1, U1, b1, W2, U2, b2);
    dense_softmax_kernel<<<BATCH, 256>>>(Wd, bd, out);
}

// round 4
// speedup vs baseline: 1.7127x; 1.6221x over previous
#include <cuda_runtime.h>
#include <math.h>

#define BATCH 128
#define TSEQ  1024
#define DIN   128
#define HID   256
#define FOURH 1024
#define DOUT  1000
#define NCTA  128

// Scratch (device globals: allocation-free)
__device__ float d_xT[(size_t)TSEQ * DIN * BATCH];     // [t][k][b]  64 MB
__device__ float d_h1[2 * HID * BATCH];                // ping-pong [parity][j][b]
__device__ float d_h2[2 * HID * BATCH];
__device__ int   g_flags[NCTA];

typedef unsigned long long ull;

__device__ __forceinline__ ull pack2(float lo, float hi) {
    ull r; asm("mov.b64 %0, {%1, %2};" : "=l"(r) : "f"(lo), "f"(hi)); return r;
}
__device__ __forceinline__ ull bcast2(float v) {
    ull r; asm("mov.b64 %0, {%1, %1};" : "=l"(r) : "f"(v)); return r;
}
__device__ __forceinline__ void upk(ull v, float& lo, float& hi) {
    asm("mov.b64 {%0, %1}, %2;" : "=f"(lo), "=f"(hi) : "l"(v));
}
__device__ __forceinline__ void ffma2(ull& d, ull a, ull b) {
    asm("fma.rn.f32x2 %0, %1, %2, %0;" : "+l"(d) : "l"(a), "l"(b));
}
__device__ __forceinline__ float sigmoidf(float z) {
    return __fdividef(1.0f, 1.0f + __expf(-z));
}

// ---------------------------------------------------------------------------
// Kernel 1: transpose x [B][T][D] -> d_xT [T][D][B]; also zero state + flags.
// ---------------------------------------------------------------------------
__global__ void transpose_x_kernel(const float* __restrict__ x) {
    __shared__ float tile[32][129];
    const int t  = blockIdx.x;
    const int b0 = blockIdx.y * 32;
    if (blockIdx.y == 0) {
        int i = blockIdx.x * 256 + threadIdx.x;
        if (i < 2 * HID * BATCH) { d_h1[i] = 0.0f; d_h2[i] = 0.0f; }
        if (blockIdx.x == 0 && threadIdx.x < NCTA) g_flags[threadIdx.x] = 0;
    }
    for (int idx = threadIdx.x; idx < 32 * 128; idx += 256) {
        int r = idx >> 7, k = idx & 127;
        tile[r][k] = x[(size_t)(b0 + r) * (TSEQ * DIN) + (size_t)t * DIN + k];
    }
    __syncthreads();
    for (int idx = threadIdx.x; idx < 32 * 128; idx += 256) {
        int k = idx >> 5, bb = idx & 31;
        d_xT[((size_t)t * DIN + k) * BATCH + b0 + bb] = tile[bb][k];
    }
}

// ---------------------------------------------------------------------------
// Kernel 2: persistent 2-layer LSTM + fused dense/softmax.
// 128 CTAs x 512 threads. CTA owns hidden units {2*cta, 2*cta+1} of both
// layers. Thread (b = tid&127, q = tid>>7): quarter q covers k in
// [64q,64q+64) of the U1/W2/U2 dots and [32q,32q+32) of x@W1.
// Layer 2 runs one step behind layer 1 -> one grid barrier per step.
// ---------------------------------------------------------------------------
__global__ void __launch_bounds__(512, 1)
lstm_persistent(const float* __restrict__ W1, const float* __restrict__ U1,
                const float* __restrict__ b1, const float* __restrict__ W2,
                const float* __restrict__ U2, const float* __restrict__ b2,
                const float* __restrict__ Wd, const float* __restrict__ bd,
                float* __restrict__ out) {
    extern __shared__ __align__(16) char dyn[];
    ull (*sU1)[4] = (ull (*)[4])dyn;            // 256 rows
    ull (*sW2)[4] = sU1 + 256;                  // 256 rows
    ull (*sU2)[4] = sW2 + 256;                  // 256 rows
    ull (*sW1)[4] = sU2 + 256;                  // 128 rows
    ull* redb = (ull*)(sW1 + 128);              // red[3][16][128]
#define RED(qm1, s, bb) redb[(size_t)(qm1) * 2048 + (s) * 128 + (bb)]

    const int tid = threadIdx.x;
    const int b   = tid & 127;
    const int q   = tid >> 7;
    const int u0  = 2 * blockIdx.x;

    // Pack weights: column pairs -> 64-bit words.
    // local col c = u*4 + g (u in {0,1}, gates i,f,g,o); global col = g*HID + u0+u
    if (tid < 256) {
        int k = tid;
#pragma unroll
        for (int p = 0; p < 4; ++p) {
            int cA = 2 * p, cB = 2 * p + 1;
            int gcA = (cA & 3) * HID + u0 + (cA >> 2);
            int gcB = (cB & 3) * HID + u0 + (cB >> 2);
            sU1[k][p] = pack2(U1[k * FOURH + gcA], U1[k * FOURH + gcB]);
            sW2[k][p] = pack2(W2[k * FOURH + gcA], W2[k * FOURH + gcB]);
            sU2[k][p] = pack2(U2[k * FOURH + gcA], U2[k * FOURH + gcB]);
            if (k < 128)
                sW1[k][p] = pack2(W1[k * FOURH + gcA], W1[k * FOURH + gcB]);
        }
    }

    float B1g[8], B2g[8];
    if (q == 0) {
#pragma unroll
        for (int c = 0; c < 8; ++c) {
            int gc = (c & 3) * HID + u0 + (c >> 2);
            B1g[c] = b1[gc];
            B2g[c] = b2[gc];
        }
    }
    float c1s0 = 0.f, c1s1 = 0.f, c2s0 = 0.f, c2s1 = 0.f;
    __syncthreads();

    const int kh = 64 * q;   // hidden k base for this quarter
    const int kx = 32 * q;   // x k base for this quarter

    for (int iter = 0; iter <= TSEQ; ++iter) {
        const int rp = iter & 1, wp = rp ^ 1;
        const float* __restrict__ hp1 = d_h1 + rp * (HID * BATCH) + kh * BATCH + b;
        const float* __restrict__ hp2 = d_h2 + rp * (HID * BATCH) + kh * BATCH + b;
        const int tx = (iter < TSEQ) ? iter : (TSEQ - 1);
        const float* __restrict__ xp = d_xT + (size_t)tx * (DIN * BATCH) + kx * BATCH + b;

        ull a1[4] = {0,0,0,0}, aW[4] = {0,0,0,0}, aU[4] = {0,0,0,0}, aX[4] = {0,0,0,0};
        float Ah1[8], Ah2[8], Ax[8], Bh1[8], Bh2[8], Bx[8];

#pragma unroll
        for (int j = 0; j < 8; ++j) {
            Ah1[j] = __ldcg(hp1 + j * BATCH);
            Ah2[j] = __ldcg(hp2 + j * BATCH);
            Ax[j]  = __ldcg(xp + j * BATCH);
        }
#pragma unroll
        for (int i = 0; i < 4; ++i) {
            const int kb = i * 16;
            // prefetch B buffers: k = kb+8 .. kb+15
#pragma unroll
            for (int j = 0; j < 8; ++j) {
                Bh1[j] = __ldcg(hp1 + (kb + 8 + j) * BATCH);
                Bh2[j] = __ldcg(hp2 + (kb + 8 + j) * BATCH);
            }
            if (i < 2) {
#pragma unroll
                for (int j = 0; j < 8; ++j) Bx[j] = __ldcg(xp + (kb + 8 + j) * BATCH);
            }
            // compute A: k = kb .. kb+7
#pragma unroll
            for (int j = 0; j < 8; ++j) {
                const int ks = kh + kb + j;
                ull hb1 = bcast2(Ah1[j]);
                ull hb2 = bcast2(Ah2[j]);
                ulonglong2 wa = *(const ulonglong2*)&sU1[ks][0];
                ulonglong2 wb = *(const ulonglong2*)&sU1[ks][2];
                ffma2(a1[0], wa.x, hb1); ffma2(a1[1], wa.y, hb1);
                ffma2(a1[2], wb.x, hb1); ffma2(a1[3], wb.y, hb1);
                wa = *(const ulonglong2*)&sW2[ks][0];
                wb = *(const ulonglong2*)&sW2[ks][2];
                ffma2(aW[0], wa.x, hb1); ffma2(aW[1], wa.y, hb1);
                ffma2(aW[2], wb.x, hb1); ffma2(aW[3], wb.y, hb1);
                wa = *(const ulonglong2*)&sU2[ks][0];
                wb = *(const ulonglong2*)&sU2[ks][2];
                ffma2(aU[0], wa.x, hb2); ffma2(aU[1], wa.y, hb2);
                ffma2(aU[2], wb.x, hb2); ffma2(aU[3], wb.y, hb2);
                if (i < 2) {
                    ull xb = bcast2(Ax[j]);
                    const int xs = kx + kb + j;
                    wa = *(const ulonglong2*)&sW1[xs][0];
                    wb = *(const ulonglong2*)&sW1[xs][2];
                    ffma2(aX[0], wa.x, xb); ffma2(aX[1], wa.y, xb);
                    ffma2(aX[2], wb.x, xb); ffma2(aX[3], wb.y, xb);
                }
            }
            // prefetch next A: k = kb+16 .. kb+23
            if (i < 3) {
#pragma unroll
                for (int j = 0; j < 8; ++j) {
                    Ah1[j] = __ldcg(hp1 + (kb + 16 + j) * BATCH);
                    Ah2[j] = __ldcg(hp2 + (kb + 16 + j) * BATCH);
                }
            }
            if (i < 1) {
#pragma unroll
                for (int j = 0; j < 8; ++j) Ax[j] = __ldcg(xp + (kb + 16 + j) * BATCH);
            }
            // compute B: k = kb+8 .. kb+15
#pragma unroll
            for (int j = 0; j < 8; ++j) {
                const int ks = kh + kb + 8 + j;
                ull hb1 = bcast2(Bh1[j]);
                ull hb2 = bcast2(Bh2[j]);
                ulonglong2 wa = *(const ulonglong2*)&sU1[ks][0];
                ulonglong2 wb = *(const ulonglong2*)&sU1[ks][2];
                ffma2(a1[0], wa.x, hb1); ffma2(a1[1], wa.y, hb1);
                ffma2(a1[2], wb.x, hb1); ffma2(a1[3], wb.y, hb1);
                wa = *(const ulonglong2*)&sW2[ks][0];
                wb = *(const ulonglong2*)&sW2[ks][2];
                ffma2(aW[0], wa.x, hb1); ffma2(aW[1], wa.y, hb1);
                ffma2(aW[2], wb.x, hb1); ffma2(aW[3], wb.y, hb1);
                wa = *(const ulonglong2*)&sU2[ks][0];
                wb = *(const ulonglong2*)&sU2[ks][2];
                ffma2(aU[0], wa.x, hb2); ffma2(aU[1], wa.y, hb2);
                ffma2(aU[2], wb.x, hb2); ffma2(aU[3], wb.y, hb2);
                if (i < 2) {
                    ull xb = bcast2(Bx[j]);
                    const int xs = kx + kb + 8 + j;
                    wa = *(const ulonglong2*)&sW1[xs][0];
                    wb = *(const ulonglong2*)&sW1[xs][2];
                    ffma2(aX[0], wa.x, xb); ffma2(aX[1], wa.y, xb);
                    ffma2(aX[2], wb.x, xb); ffma2(aX[3], wb.y, xb);
                }
            }
        }

        // Cross-quarter reduction: quarters 1..3 publish partials
        if (q != 0) {
            const int m = q - 1;
#pragma unroll
            for (int p = 0; p < 4; ++p) {
                RED(m, p, b)      = a1[p];
                RED(m, 4 + p, b)  = aW[p];
                RED(m, 8 + p, b)  = aU[p];
                RED(m, 12 + p, b) = aX[p];
            }
        }
        __syncthreads();

        if (q == 0) {
            float z1[8], zW[8], zU[8];
#pragma unroll
            for (int p = 0; p < 4; ++p) {
                float lo, hi, t0, t1;
                upk(a1[p], lo, hi);
                upk(aX[p], t0, t1); lo += t0; hi += t1;
#pragma unroll
                for (int m = 0; m < 3; ++m) {
                    upk(RED(m, p, b), t0, t1);      lo += t0; hi += t1;
                    upk(RED(m, 12 + p, b), t0, t1); lo += t0; hi += t1;
                }
                z1[2 * p] = lo; z1[2 * p + 1] = hi;
                upk(aW[p], lo, hi);
#pragma unroll
                for (int m = 0; m < 3; ++m) {
                    upk(RED(m, 4 + p, b), t0, t1); lo += t0; hi += t1;
                }
                zW[2 * p] = lo; zW[2 * p + 1] = hi;
                upk(aU[p], lo, hi);
#pragma unroll
                for (int m = 0; m < 3; ++m) {
                    upk(RED(m, 8 + p, b), t0, t1); lo += t0; hi += t1;
                }
                zU[2 * p] = lo; zU[2 * p + 1] = hi;
            }
            if (iter < TSEQ) {
#pragma unroll
                for (int u = 0; u < 2; ++u) {
                    int cb = 4 * u;
                    float zi = z1[cb] + B1g[cb];
                    float zf = z1[cb + 1] + B1g[cb + 1];
                    float zg = z1[cb + 2] + B1g[cb + 2];
                    float zo = z1[cb + 3] + B1g[cb + 3];
                    float ig = sigmoidf(zi), fg = sigmoidf(zf);
                    float gv = fmaxf(zg, 0.f), og = sigmoidf(zo);
                    float c = (u == 0) ? c1s0 : c1s1;
                    c = fg * c + ig * gv;
                    if (u == 0) c1s0 = c; else c1s1 = c;
                    __stcg(&d_h1[wp * (HID * BATCH) + (u0 + u) * BATCH + b],
                           og * fmaxf(c, 0.f));
                }
            }
            if (iter >= 1) {
#pragma unroll
                for (int u = 0; u < 2; ++u) {
                    int cb = 4 * u;
                    float zi = zW[cb] + zU[cb] + B2g[cb];
                    float zf = zW[cb + 1] + zU[cb + 1] + B2g[cb + 1];
                    float zg = zW[cb + 2] + zU[cb + 2] + B2g[cb + 2];
                    float zo = zW[cb + 3] + zU[cb + 3] + B2g[cb + 3];
                    float ig = sigmoidf(zi), fg = sigmoidf(zf);
                    float gv = fmaxf(zg, 0.f), og = sigmoidf(zo);
                    float c = (u == 0) ? c2s0 : c2s1;
                    c = fg * c + ig * gv;
                    if (u == 0) c2s0 = c; else c2s1 = c;
                    __stcg(&d_h2[wp * (HID * BATCH) + (u0 + u) * BATCH + b],
                           og * fmaxf(c, 0.f));
                }
            }
        }

        // Grid barrier (flag per CTA; release/acquire covers the .cg stores)
        __syncthreads();
        if (tid == 0) {
            asm volatile("st.release.gpu.global.s32 [%0], %1;"
                         :: "l"(g_flags + blockIdx.x), "r"(iter + 1) : "memory");
        }
        if (tid < 32) {
            const int tgt = iter + 1;
            int ok;
            do {
                ok = 1;
#pragma unroll
                for (int s = 0; s < NCTA / 32; ++s) {
                    int v;
                    asm volatile("ld.acquire.gpu.global.s32 %0, [%1];"
                                 : "=r"(v) : "l"(g_flags + s * 32 + tid));
                    ok &= (v >= tgt);
                }
            } while (!__all_sync(0xffffffffu, ok));
        }
        __syncthreads();
    }

    // ---------------- Dense + softmax (CTA = one batch row) ----------------
    // h_last = d_h2 parity 1 (iter TSEQ wrote wp = 1).
    {
        const int bb = blockIdx.x;
        float* lg  = (float*)redb;        // [1024] logits
        float* shh = lg + 1024;           // [256] h
        float* rb  = shh + 256;           // [16] warp partials

        if (tid < 256)
            shh[tid] = __ldcg(&d_h2[HID * BATCH + tid * BATCH + bb]);
        __syncthreads();

        const int o0 = tid, o1 = tid + 512;
        float acc0 = (o0 < DOUT) ? bd[o0] : -1e30f;
        float acc1 = (o1 < DOUT) ? bd[o1] : -1e30f;
#pragma unroll 8
        for (int k = 0; k < HID; ++k) {
            float h = shh[k];
            const float* wrow = Wd + (size_t)k * DOUT;
            if (o0 < DOUT) acc0 += h * wrow[o0];
            if (o1 < DOUT) acc1 += h * wrow[o1];
        }
        float lmax = fmaxf(acc0, acc1);
#pragma unroll
        for (int off = 16; off; off >>= 1)
            lmax = fmaxf(lmax, __shfl_xor_sync(0xffffffffu, lmax, off));
        if ((tid & 31) == 0) rb[tid >> 5] = lmax;
        __syncthreads();
        if (tid == 0) {
            float m = rb[0];
#pragma unroll
            for (int i = 1; i < 16; ++i) m = fmaxf(m, rb[i]);
            rb[0] = m;
        }
        __syncthreads();
        const float M = rb[0];
        __syncthreads();

        float e0 = (o0 < DOUT) ? __expf(acc0 - M) : 0.f;
        float e1 = (o1 < DOUT) ? __expf(acc1 - M) : 0.f;
        float lsum = e0 + e1;
#pragma unroll
        for (int off = 16; off; off >>= 1)
            lsum += __shfl_xor_sync(0xffffffffu, lsum, off);
        if ((tid & 31) == 0) rb[tid >> 5] = lsum;
        __syncthreads();
        if (tid == 0) {
            float s = 0.f;
#pragma unroll
            for (int i = 0; i < 16; ++i) s += rb[i];
            rb[0] = s;
        }
        __syncthreads();
        const float inv = __fdividef(1.0f, rb[0]);
        if (o0 < DOUT) out[(size_t)bb * DOUT + o0] = e0 * inv;
        if (o1 < DOUT) out[(size_t)bb * DOUT + o1] = e1 * inv;
    }
}

// ---------------------------------------------------------------------------
static const int SMEM_BYTES = (256 * 3 + 128) * 4 * 8 /*weights*/ +
                              3 * 16 * 128 * 8 /*red*/;  // 77,824 B

extern "C" void kernel_launch(void* const* d_in, const int* in_sizes, int n_in,
                              void* d_out, int out_size) {
    const float* x  = (const float*)d_in[0];
    const float* W1 = (const float*)d_in[1];
    const float* U1 = (const float*)d_in[2];
    const float* b1 = (const float*)d_in[3];
    const float* W2 = (const float*)d_in[4];
    const float* U2 = (const float*)d_in[5];
    const float* b2 = (const float*)d_in[6];
    const float* Wd = (const float*)d_in[7];
    const float* bd = (const float*)d_in[8];
    float* out = (float*)d_out;

    static int attr_set = 0;
    if (!attr_set) {
        cudaFuncSetAttribute(lstm_persistent,
                             cudaFuncAttributeMaxDynamicSharedMemorySize,
                             SMEM_BYTES);
        attr_set = 1;
    }

    transpose_x_kernel<<<dim3(TSEQ, 4), 256>>>(x);
    lstm_persistent<<<NCTA, 512, SMEM_BYTES>>>(W1, U1, b1, W2, U2, b2,
                                               Wd, bd, out);
}

// round 5
// speedup vs baseline: 2.2946x; 1.3397x over previous
#include <cuda_runtime.h>
#include <math.h>

#define BATCH 128
#define TSEQ  1024
#define DIN   128
#define HID   256
#define FOURH 1024
#define DOUT  1000
#define NCTA  128
#define HB    (HID * BATCH)

// Scratch (device globals: allocation-free)
__device__ float d_xT[(size_t)TSEQ * DIN * BATCH];     // [t][k][b]  64 MB
__device__ float d_h1[2 * HB];                          // ping-pong [parity][j][b]
__device__ float d_h2[2 * HB];
__device__ int   g_flags[NCTA];

typedef unsigned long long ull;

__device__ __forceinline__ ull pack2(float lo, float hi) {
    ull r; asm("mov.b64 %0, {%1, %2};" : "=l"(r) : "f"(lo), "f"(hi)); return r;
}
__device__ __forceinline__ ull bcast2(float v) {
    ull r; asm("mov.b64 %0, {%1, %1};" : "=l"(r) : "f"(v)); return r;
}
__device__ __forceinline__ void upk(ull v, float& lo, float& hi) {
    asm("mov.b64 {%0, %1}, %2;" : "=f"(lo), "=f"(hi) : "l"(v));
}
__device__ __forceinline__ void ffma2(ull& d, ull a, ull b) {
    asm("fma.rn.f32x2 %0, %1, %2, %0;" : "+l"(d) : "l"(a), "l"(b));
}
__device__ __forceinline__ float sigmoidf(float z) {
    return __fdividef(1.0f, 1.0f + __expf(-z));
}

// ---------------------------------------------------------------------------
// Kernel 1: transpose x [B][T][D] -> d_xT [T][D][B]; also zero state + flags.
// ---------------------------------------------------------------------------
__global__ void transpose_x_kernel(const float* __restrict__ x) {
    __shared__ float tile[32][129];
    const int t  = blockIdx.x;
    const int b0 = blockIdx.y * 32;
    if (blockIdx.y == 0) {
        int i = blockIdx.x * 256 + threadIdx.x;
        if (i < 2 * HB) { d_h1[i] = 0.0f; d_h2[i] = 0.0f; }
        if (blockIdx.x == 0 && threadIdx.x < NCTA) g_flags[threadIdx.x] = 0;
    }
    for (int idx = threadIdx.x; idx < 32 * 128; idx += 256) {
        int r = idx >> 7, k = idx & 127;
        tile[r][k] = x[(size_t)(b0 + r) * (TSEQ * DIN) + (size_t)t * DIN + k];
    }
    __syncthreads();
    for (int idx = threadIdx.x; idx < 32 * 128; idx += 256) {
        int k = idx >> 5, bb = idx & 31;
        d_xT[((size_t)t * DIN + k) * BATCH + b0 + bb] = tile[bb][k];
    }
}

// ---------------------------------------------------------------------------
// Kernel 2: persistent 2-layer LSTM + fused dense/softmax.
// 128 CTAs x 512 threads; CTA owns hidden units {2*cta, 2*cta+1} of both
// layers (8 gate-cols). Dot phase: thread (bb = tid&63, s = tid>>6) covers
// batches {bb, bb+64} and k-slice [32s,32s+32) (hidden) / [16s,16s+16) (x).
// x@W1 folds into the a1 accumulators. Epilogue: thread (b=tid&127,
// u=(tid>>7)&1, layer=tid>>8) reduces 8 slice-partials and owns its c-state.
// Layer 2 runs one step behind layer 1 -> one grid barrier per step.
// ---------------------------------------------------------------------------
__global__ void __launch_bounds__(512, 1)
lstm_persistent(const float* __restrict__ W1, const float* __restrict__ U1,
                const float* __restrict__ b1, const float* __restrict__ W2,
                const float* __restrict__ U2, const float* __restrict__ b2,
                const float* __restrict__ Wd, const float* __restrict__ bd,
                float* __restrict__ out) {
    extern __shared__ __align__(16) char dyn[];
    ull (*sU1)[4] = (ull (*)[4])dyn;            // 256 rows (U1, h1 input)
    ull (*sW2)[4] = sU1 + 256;                  // 256 rows (W2, h1 input)
    ull (*sU2)[4] = sW2 + 256;                  // 256 rows (U2, h2 input)
    ull (*sW1)[4] = sU2 + 256;                  // 128 rows (W1, x input)
    ull* red = (ull*)(sW1 + 128);               // [12][8][128]
#define RED(p, ss, bbx) red[((p) << 10) + ((ss) << 7) + (bbx)]

    const int tid = threadIdx.x;
    const int bb  = tid & 63;
    const int s   = tid >> 6;          // k-slice 0..7
    const int u0  = 2 * blockIdx.x;

    // Pack weights: column pairs -> 64-bit words.
    // local col c = u*4 + g (u in {0,1}, gates i,f,g,o); global col = g*HID + u0+u
    if (tid < 256) {
        int k = tid;
#pragma unroll
        for (int p = 0; p < 4; ++p) {
            int cA = 2 * p, cB = 2 * p + 1;
            int gcA = (cA & 3) * HID + u0 + (cA >> 2);
            int gcB = (cB & 3) * HID + u0 + (cB >> 2);
            sU1[k][p] = pack2(U1[k * FOURH + gcA], U1[k * FOURH + gcB]);
            sW2[k][p] = pack2(W2[k * FOURH + gcA], W2[k * FOURH + gcB]);
            sU2[k][p] = pack2(U2[k * FOURH + gcA], U2[k * FOURH + gcB]);
            if (k < 128)
                sW1[k][p] = pack2(W1[k * FOURH + gcA], W1[k * FOURH + gcB]);
        }
    }

    // Epilogue identity + biases + owned cell state
    const int eb   = tid & 127;
    const int eu   = (tid >> 7) & 1;
    const int elay = tid >> 8;
    float EB[4];
#pragma unroll
    for (int g = 0; g < 4; ++g) {
        int gc = g * HID + u0 + eu;
        EB[g] = elay ? b2[gc] : b1[gc];
    }
    float ec = 0.0f;
    __syncthreads();

    const int kh = 32 * s;   // hidden k base
    const int kx = 16 * s;   // x k base

    for (int iter = 0; iter <= TSEQ; ++iter) {
        const int rp = iter & 1, wp = rp ^ 1;
        const float* __restrict__ hp1 = d_h1 + rp * HB + kh * BATCH + bb;
        const float* __restrict__ hp2 = d_h2 + rp * HB + kh * BATCH + bb;
        const int tx = (iter < TSEQ) ? iter : (TSEQ - 1);
        const float* __restrict__ xp = d_xT + (size_t)tx * (DIN * BATCH) + kx * BATCH + bb;

        ull a1[2][4] = {{0,0,0,0},{0,0,0,0}};
        ull aW[2][4] = {{0,0,0,0},{0,0,0,0}};
        ull aU[2][4] = {{0,0,0,0},{0,0,0,0}};

        // ---- x part (16 k), folded into a1 ----
        {
            float X[32];
#pragma unroll
            for (int j = 0; j < 16; ++j) {
                X[2 * j]     = __ldcg(xp + j * BATCH);
                X[2 * j + 1] = __ldcg(xp + j * BATCH + 64);
            }
#pragma unroll
            for (int j = 0; j < 16; ++j) {
                const int k = kx + j;
                ull xa = bcast2(X[2 * j]);
                ull xb = bcast2(X[2 * j + 1]);
                ulonglong2 wa = *(const ulonglong2*)&sW1[k][0];
                ulonglong2 wb = *(const ulonglong2*)&sW1[k][2];
                ffma2(a1[0][0], wa.x, xa); ffma2(a1[0][1], wa.y, xa);
                ffma2(a1[0][2], wb.x, xa); ffma2(a1[0][3], wb.y, xa);
                ffma2(a1[1][0], wa.x, xb); ffma2(a1[1][1], wa.y, xb);
                ffma2(a1[1][2], wb.x, xb); ffma2(a1[1][3], wb.y, xb);
            }
        }

        // ---- hidden part (32 k), 4-k double-buffered pipeline ----
        {
            float Ha[16], Hbuf[16];
#pragma unroll
            for (int j = 0; j < 4; ++j) {
                Ha[4 * j + 0] = __ldcg(hp1 + j * BATCH);
                Ha[4 * j + 1] = __ldcg(hp1 + j * BATCH + 64);
                Ha[4 * j + 2] = __ldcg(hp2 + j * BATCH);
                Ha[4 * j + 3] = __ldcg(hp2 + j * BATCH + 64);
            }
#pragma unroll
            for (int blk = 0; blk < 8; ++blk) {
                float* cur = (blk & 1) ? Hbuf : Ha;
                float* nxt = (blk & 1) ? Ha : Hbuf;
                if (blk < 7) {
                    const int kn = (blk + 1) * 4;
#pragma unroll
                    for (int j = 0; j < 4; ++j) {
                        nxt[4 * j + 0] = __ldcg(hp1 + (kn + j) * BATCH);
                        nxt[4 * j + 1] = __ldcg(hp1 + (kn + j) * BATCH + 64);
                        nxt[4 * j + 2] = __ldcg(hp2 + (kn + j) * BATCH);
                        nxt[4 * j + 3] = __ldcg(hp2 + (kn + j) * BATCH + 64);
                    }
                }
#pragma unroll
                for (int j = 0; j < 4; ++j) {
                    const int k = kh + blk * 4 + j;
                    ull h1a = bcast2(cur[4 * j + 0]);
                    ull h1b = bcast2(cur[4 * j + 1]);
                    ull h2a = bcast2(cur[4 * j + 2]);
                    ull h2b = bcast2(cur[4 * j + 3]);
                    ulonglong2 wa = *(const ulonglong2*)&sU1[k][0];
                    ulonglong2 wb = *(const ulonglong2*)&sU1[k][2];
                    ffma2(a1[0][0], wa.x, h1a); ffma2(a1[0][1], wa.y, h1a);
                    ffma2(a1[0][2], wb.x, h1a); ffma2(a1[0][3], wb.y, h1a);
                    ffma2(a1[1][0], wa.x, h1b); ffma2(a1[1][1], wa.y, h1b);
                    ffma2(a1[1][2], wb.x, h1b); ffma2(a1[1][3], wb.y, h1b);
                    wa = *(const ulonglong2*)&sW2[k][0];
                    wb = *(const ulonglong2*)&sW2[k][2];
                    ffma2(aW[0][0], wa.x, h1a); ffma2(aW[0][1], wa.y, h1a);
                    ffma2(aW[0][2], wb.x, h1a); ffma2(aW[0][3], wb.y, h1a);
                    ffma2(aW[1][0], wa.x, h1b); ffma2(aW[1][1], wa.y, h1b);
                    ffma2(aW[1][2], wb.x, h1b); ffma2(aW[1][3], wb.y, h1b);
                    wa = *(const ulonglong2*)&sU2[k][0];
                    wb = *(const ulonglong2*)&sU2[k][2];
                    ffma2(aU[0][0], wa.x, h2a); ffma2(aU[0][1], wa.y, h2a);
                    ffma2(aU[0][2], wb.x, h2a); ffma2(aU[0][3], wb.y, h2a);
                    ffma2(aU[1][0], wa.x, h2b); ffma2(aU[1][1], wa.y, h2b);
                    ffma2(aU[1][2], wb.x, h2b); ffma2(aU[1][3], wb.y, h2b);
                }
            }
        }

        // ---- publish slice partials ----
#pragma unroll
        for (int p = 0; p < 4; ++p) {
            RED(p, s, bb)          = a1[0][p];
            RED(p, s, bb + 64)     = a1[1][p];
            RED(4 + p, s, bb)      = aW[0][p];
            RED(4 + p, s, bb + 64) = aW[1][p];
            RED(8 + p, s, bb)      = aU[0][p];
            RED(8 + p, s, bb + 64) = aU[1][p];
        }
        __syncthreads();

        // ---- epilogue: thread (eb, eu, elay) ----
        if (elay == 0) {
            if (iter < TSEQ) {
                float z[4];
#pragma unroll
                for (int pi = 0; pi < 2; ++pi) {
                    const int p = 2 * eu + pi;
                    float lo = 0.f, hi = 0.f, t0, t1;
#pragma unroll
                    for (int s2 = 0; s2 < 8; ++s2) {
                        upk(RED(p, s2, eb), t0, t1);
                        lo += t0; hi += t1;
                    }
                    z[2 * pi] = lo; z[2 * pi + 1] = hi;
                }
                float ig = sigmoidf(z[0] + EB[0]);
                float fg = sigmoidf(z[1] + EB[1]);
                float gv = fmaxf(z[2] + EB[2], 0.f);
                float og = sigmoidf(z[3] + EB[3]);
                ec = fg * ec + ig * gv;
                __stcg(&d_h1[wp * HB + (u0 + eu) * BATCH + eb],
                       og * fmaxf(ec, 0.f));
            }
        } else {
            if (iter >= 1) {
                float z[4];
#pragma unroll
                for (int pi = 0; pi < 2; ++pi) {
                    const int p = 2 * eu + pi;
                    float lo = 0.f, hi = 0.f, t0, t1;
#pragma unroll
                    for (int s2 = 0; s2 < 8; ++s2) {
                        upk(RED(4 + p, s2, eb), t0, t1);
                        lo += t0; hi += t1;
                        upk(RED(8 + p, s2, eb), t0, t1);
                        lo += t0; hi += t1;
                    }
                    z[2 * pi] = lo; z[2 * pi + 1] = hi;
                }
                float ig = sigmoidf(z[0] + EB[0]);
                float fg = sigmoidf(z[1] + EB[1]);
                float gv = fmaxf(z[2] + EB[2], 0.f);
                float og = sigmoidf(z[3] + EB[3]);
                ec = fg * ec + ig * gv;
                __stcg(&d_h2[wp * HB + (u0 + eu) * BATCH + eb],
                       og * fmaxf(ec, 0.f));
            }
        }

        // ---- grid barrier ----
        __syncthreads();
        if (tid == 0) {
            asm volatile("st.release.gpu.global.s32 [%0], %1;"
                         :: "l"(g_flags + blockIdx.x), "r"(iter + 1) : "memory");
        }
        if (tid < 32) {
            const int tgt = iter + 1;
            int ok;
            do {
                ok = 1;
#pragma unroll
                for (int q = 0; q < NCTA / 32; ++q) {
                    int v;
                    asm volatile("ld.acquire.gpu.global.s32 %0, [%1];"
                                 : "=r"(v) : "l"(g_flags + q * 32 + tid));
                    ok &= (v >= tgt);
                }
            } while (!__all_sync(0xffffffffu, ok));
        }
        __syncthreads();
    }

    // ---------------- Dense + softmax (CTA = one batch row) ----------------
    // h_last = d_h2 parity 1 (iter TSEQ wrote wp = 1).
    {
        const int brow = blockIdx.x;
        float* shh = (float*)red;          // [256] h
        float* rb  = shh + 256;            // [16] warp partials

        if (tid < 256)
            shh[tid] = __ldcg(&d_h2[HB + tid * BATCH + brow]);
        __syncthreads();

        const int o0 = tid, o1 = tid + 512;
        float acc0 = (o0 < DOUT) ? bd[o0] : -1e30f;
        float acc1 = (o1 < DOUT) ? bd[o1] : -1e30f;
#pragma unroll 8
        for (int k = 0; k < HID; ++k) {
            float h = shh[k];
            const float* wrow = Wd + (size_t)k * DOUT;
            if (o0 < DOUT) acc0 += h * wrow[o0];
            if (o1 < DOUT) acc1 += h * wrow[o1];
        }
        float lmax = fmaxf(acc0, acc1);
#pragma unroll
        for (int off = 16; off; off >>= 1)
            lmax = fmaxf(lmax, __shfl_xor_sync(0xffffffffu, lmax, off));
        if ((tid & 31) == 0) rb[tid >> 5] = lmax;
        __syncthreads();
        if (tid == 0) {
            float m = rb[0];
#pragma unroll
            for (int i = 1; i < 16; ++i) m = fmaxf(m, rb[i]);
            rb[0] = m;
        }
        __syncthreads();
        const float M = rb[0];
        __syncthreads();

        float e0 = (o0 < DOUT) ? __expf(acc0 - M) : 0.f;
        float e1 = (o1 < DOUT) ? __expf(acc1 - M) : 0.f;
        float lsum = e0 + e1;
#pragma unroll
        for (int off = 16; off; off >>= 1)
            lsum += __shfl_xor_sync(0xffffffffu, lsum, off);
        if ((tid & 31) == 0) rb[tid >> 5] = lsum;
        __syncthreads();
        if (tid == 0) {
            float sm = 0.f;
#pragma unroll
            for (int i = 0; i < 16; ++i) sm += rb[i];
            rb[0] = sm;
        }
        __syncthreads();
        const float inv = __fdividef(1.0f, rb[0]);
        if (o0 < DOUT) out[(size_t)brow * DOUT + o0] = e0 * inv;
        if (o1 < DOUT) out[(size_t)brow * DOUT + o1] = e1 * inv;
    }
}

// ---------------------------------------------------------------------------
static const int SMEM_BYTES = (256 * 3 + 128) * 4 * 8 /*weights 28,672*/ +
                              12 * 8 * 128 * 8 /*red 98,304*/;  // 126,976 B

extern "C" void kernel_launch(void* const* d_in, const int* in_sizes, int n_in,
                              void* d_out, int out_size) {
    const float* x  = (const float*)d_in[0];
    const float* W1 = (const float*)d_in[1];
    const float* U1 = (const float*)d_in[2];
    const float* b1 = (const float*)d_in[3];
    const float* W2 = (const float*)d_in[4];
    const float* U2 = (const float*)d_in[5];
    const float* b2 = (const float*)d_in[6];
    const float* Wd = (const float*)d_in[7];
    const float* bd = (const float*)d_in[8];
    float* out = (float*)d_out;

    cudaFuncSetAttribute(lstm_persistent,
                         cudaFuncAttributeMaxDynamicSharedMemorySize,
                         SMEM_BYTES);

    transpose_x_kernel<<<dim3(TSEQ, 4), 256>>>(x);
    lstm_persistent<<<NCTA, 512, SMEM_BYTES>>>(W1, U1, b1, W2, U2, b2,
                                               Wd, bd, out);
}

// round 7
// speedup vs baseline: 2.6537x; 1.1565x over previous
#include <cuda_runtime.h>
#include <math.h>

#define BATCH 128
#define TSEQ  1024
#define DIN   128
#define HID   256
#define FOURH 1024
#define DOUT  1000
#define NCTA  128
#define HB    (HID * BATCH)

// Scratch (device globals: allocation-free)
__device__ float d_xT[(size_t)TSEQ * DIN * BATCH];     // [t][k][b]  64 MB
__device__ float d_h1[2 * HB];                          // ping-pong [parity][j][b]
__device__ float d_h2[2 * HB];
__device__ int   g_cnt;

typedef unsigned long long ull;

__device__ __forceinline__ ull pack2(float lo, float hi) {
    ull r; asm("mov.b64 %0, {%1, %2};" : "=l"(r) : "f"(lo), "f"(hi)); return r;
}
__device__ __forceinline__ ull bcast2(float v) {
    ull r; asm("mov.b64 %0, {%1, %1};" : "=l"(r) : "f"(v)); return r;
}
__device__ __forceinline__ void upk(ull v, float& lo, float& hi) {
    asm("mov.b64 {%0, %1}, %2;" : "=f"(lo), "=f"(hi) : "l"(v));
}
__device__ __forceinline__ void ffma2(ull& d, ull a, ull b) {
    asm("fma.rn.f32x2 %0, %1, %2, %0;" : "+l"(d) : "l"(a), "l"(b));
}
__device__ __forceinline__ float sigmoidf(float z) {
    return __fdividef(1.0f, 1.0f + __expf(-z));
}

// ---------------------------------------------------------------------------
// Kernel 1: transpose x [B][T][D] -> d_xT [T][D][B]; zero state + counter.
// ---------------------------------------------------------------------------
__global__ void transpose_x_kernel(const float* __restrict__ x) {
    __shared__ float tile[32][129];
    const int t  = blockIdx.x;
    const int b0 = blockIdx.y * 32;
    if (blockIdx.y == 0) {
        int i = blockIdx.x * 256 + threadIdx.x;
        if (i < 2 * HB) { d_h1[i] = 0.0f; d_h2[i] = 0.0f; }
        if (blockIdx.x == 0 && threadIdx.x == 0) g_cnt = 0;
    }
    for (int idx = threadIdx.x; idx < 32 * 128; idx += 256) {
        int r = idx >> 7, k = idx & 127;
        tile[r][k] = x[(size_t)(b0 + r) * (TSEQ * DIN) + (size_t)t * DIN + k];
    }
    __syncthreads();
    for (int idx = threadIdx.x; idx < 32 * 128; idx += 256) {
        int k = idx >> 5, bb = idx & 31;
        d_xT[((size_t)t * DIN + k) * BATCH + b0 + bb] = tile[bb][k];
    }
}

// ---------------------------------------------------------------------------
// x-part: 16 k of x@W1 for this thread's slice -> xacc (overwritten).
// ---------------------------------------------------------------------------
__device__ __forceinline__ void compute_x(
    const float* __restrict__ xp, const ull (* __restrict__ sW1)[4],
    int kx, ull (&xacc)[2][4])
{
#pragma unroll
    for (int a = 0; a < 2; ++a)
#pragma unroll
        for (int p = 0; p < 4; ++p) xacc[a][p] = 0;
    float X[32];
#pragma unroll
    for (int j = 0; j < 16; ++j) {
        X[2 * j]     = __ldcg(xp + j * BATCH);
        X[2 * j + 1] = __ldcg(xp + j * BATCH + 64);
    }
#pragma unroll
    for (int j = 0; j < 16; ++j) {
        const int k = kx + j;
        ull xa = bcast2(X[2 * j]);
        ull xb = bcast2(X[2 * j + 1]);
        ulonglong2 wa = *(const ulonglong2*)&sW1[k][0];
        ulonglong2 wb = *(const ulonglong2*)&sW1[k][2];
        ffma2(xacc[0][0], wa.x, xa); ffma2(xacc[0][1], wa.y, xa);
        ffma2(xacc[0][2], wb.x, xa); ffma2(xacc[0][3], wb.y, xa);
        ffma2(xacc[1][0], wa.x, xb); ffma2(xacc[1][1], wa.y, xb);
        ffma2(xacc[1][2], wb.x, xb); ffma2(xacc[1][3], wb.y, xb);
    }
}

// ---------------------------------------------------------------------------
// Kernel 2: persistent 2-layer LSTM + fused dense/softmax.
// 128 CTAs x 512 threads; CTA owns units {2*cta, 2*cta+1} of both layers.
// Dot: thread (bb=tid&63, s=tid>>6) covers batches {bb,bb+64}, hidden k
// [32s,32s+32), x k [16s,16s+16). x@W1(t+1) computed in the barrier shadow.
// The grid barrier runs EVERY iteration incl. the last: the fused
// dense/softmax reads other CTAs' h2 and needs the final sync.
// ---------------------------------------------------------------------------
__global__ void __launch_bounds__(512, 1)
lstm_persistent(const float* __restrict__ W1, const float* __restrict__ U1,
                const float* __restrict__ b1, const float* __restrict__ W2,
                const float* __restrict__ U2, const float* __restrict__ b2,
                const float* __restrict__ Wd, const float* __restrict__ bd,
                float* __restrict__ out) {
    extern __shared__ __align__(16) char dyn[];
    ull (*sU1)[4] = (ull (*)[4])dyn;            // 256 rows
    ull (*sW2)[4] = sU1 + 256;                  // 256 rows
    ull (*sU2)[4] = sW2 + 256;                  // 256 rows
    ull (*sW1)[4] = sU2 + 256;                  // 128 rows
    ulonglong2* red = (ulonglong2*)(sW1 + 128); // [3 streams][2 pairs][8 s][128 b]
#define RED2(st, pp, ss, bbx) red[((((st) << 1) + (pp)) << 10) + ((ss) << 7) + (bbx)]

    const int tid = threadIdx.x;
    const int bb  = tid & 63;
    const int s   = tid >> 6;          // k-slice 0..7
    const int u0  = 2 * blockIdx.x;

    // Pack weights: column pairs -> 64-bit words.
    if (tid < 256) {
        int k = tid;
#pragma unroll
        for (int p = 0; p < 4; ++p) {
            int cA = 2 * p, cB = 2 * p + 1;
            int gcA = (cA & 3) * HID + u0 + (cA >> 2);
            int gcB = (cB & 3) * HID + u0 + (cB >> 2);
            sU1[k][p] = pack2(U1[k * FOURH + gcA], U1[k * FOURH + gcB]);
            sW2[k][p] = pack2(W2[k * FOURH + gcA], W2[k * FOURH + gcB]);
            sU2[k][p] = pack2(U2[k * FOURH + gcA], U2[k * FOURH + gcB]);
            if (k < 128)
                sW1[k][p] = pack2(W1[k * FOURH + gcA], W1[k * FOURH + gcB]);
        }
    }

    // Epilogue identity + biases + owned cell state
    const int eb   = tid & 127;
    const int eu   = (tid >> 7) & 1;
    const int elay = tid >> 8;
    float EB[4];
#pragma unroll
    for (int g = 0; g < 4; ++g) {
        int gc = g * HID + u0 + eu;
        EB[g] = elay ? b2[gc] : b1[gc];
    }
    float ec = 0.0f;
    __syncthreads();

    const int kh = 32 * s;   // hidden k base
    const int kx = 16 * s;   // x k base

    ull xacc[2][4];
    compute_x(d_xT + (size_t)0 + kx * BATCH + bb, sW1, kx, xacc);

    for (int iter = 0; iter <= TSEQ; ++iter) {
        const int rp = iter & 1, wp = rp ^ 1;
        const float* __restrict__ hp1 = d_h1 + rp * HB + kh * BATCH + bb;
        const float* __restrict__ hp2 = d_h2 + rp * HB + kh * BATCH + bb;

        ull a1[2][4], aW[2][4] = {{0,0,0,0},{0,0,0,0}}, aU[2][4] = {{0,0,0,0},{0,0,0,0}};
#pragma unroll
        for (int a = 0; a < 2; ++a)
#pragma unroll
            for (int p = 0; p < 4; ++p) a1[a][p] = xacc[a][p];

        // ---- hidden part (32 k), 4-k double-buffered pipeline ----
        {
            float Ha[16], Hbuf[16];
#pragma unroll
            for (int j = 0; j < 4; ++j) {
                Ha[4 * j + 0] = __ldcg(hp1 + j * BATCH);
                Ha[4 * j + 1] = __ldcg(hp1 + j * BATCH + 64);
                Ha[4 * j + 2] = __ldcg(hp2 + j * BATCH);
                Ha[4 * j + 3] = __ldcg(hp2 + j * BATCH + 64);
            }
#pragma unroll
            for (int blk = 0; blk < 8; ++blk) {
                float* cur = (blk & 1) ? Hbuf : Ha;
                float* nxt = (blk & 1) ? Ha : Hbuf;
                if (blk < 7) {
                    const int kn = (blk + 1) * 4;
#pragma unroll
                    for (int j = 0; j < 4; ++j) {
                        nxt[4 * j + 0] = __ldcg(hp1 + (kn + j) * BATCH);
                        nxt[4 * j + 1] = __ldcg(hp1 + (kn + j) * BATCH + 64);
                        nxt[4 * j + 2] = __ldcg(hp2 + (kn + j) * BATCH);
                        nxt[4 * j + 3] = __ldcg(hp2 + (kn + j) * BATCH + 64);
                    }
                }
#pragma unroll
                for (int j = 0; j < 4; ++j) {
                    const int k = kh + blk * 4 + j;
                    ull h1a = bcast2(cur[4 * j + 0]);
                    ull h1b = bcast2(cur[4 * j + 1]);
                    ull h2a = bcast2(cur[4 * j + 2]);
                    ull h2b = bcast2(cur[4 * j + 3]);
                    ulonglong2 wa = *(const ulonglong2*)&sU1[k][0];
                    ulonglong2 wb = *(const ulonglong2*)&sU1[k][2];
                    ffma2(a1[0][0], wa.x, h1a); ffma2(a1[0][1], wa.y, h1a);
                    ffma2(a1[0][2], wb.x, h1a); ffma2(a1[0][3], wb.y, h1a);
                    ffma2(a1[1][0], wa.x, h1b); ffma2(a1[1][1], wa.y, h1b);
                    ffma2(a1[1][2], wb.x, h1b); ffma2(a1[1][3], wb.y, h1b);
                    wa = *(const ulonglong2*)&sW2[k][0];
                    wb = *(const ulonglong2*)&sW2[k][2];
                    ffma2(aW[0][0], wa.x, h1a); ffma2(aW[0][1], wa.y, h1a);
                    ffma2(aW[0][2], wb.x, h1a); ffma2(aW[0][3], wb.y, h1a);
                    ffma2(aW[1][0], wa.x, h1b); ffma2(aW[1][1], wa.y, h1b);
                    ffma2(aW[1][2], wb.x, h1b); ffma2(aW[1][3], wb.y, h1b);
                    wa = *(const ulonglong2*)&sU2[k][0];
                    wb = *(const ulonglong2*)&sU2[k][2];
                    ffma2(aU[0][0], wa.x, h2a); ffma2(aU[0][1], wa.y, h2a);
                    ffma2(aU[0][2], wb.x, h2a); ffma2(aU[0][3], wb.y, h2a);
                    ffma2(aU[1][0], wa.x, h2b); ffma2(aU[1][1], wa.y, h2b);
                    ffma2(aU[1][2], wb.x, h2b); ffma2(aU[1][3], wb.y, h2b);
                }
            }
        }

        // ---- publish slice partials (16B stores) ----
#pragma unroll
        for (int a = 0; a < 2; ++a) {
            const int bx = bb + 64 * a;
            RED2(0, 0, s, bx) = make_ulonglong2(a1[a][0], a1[a][1]);
            RED2(0, 1, s, bx) = make_ulonglong2(a1[a][2], a1[a][3]);
            RED2(1, 0, s, bx) = make_ulonglong2(aW[a][0], aW[a][1]);
            RED2(1, 1, s, bx) = make_ulonglong2(aW[a][2], aW[a][3]);
            RED2(2, 0, s, bx) = make_ulonglong2(aU[a][0], aU[a][1]);
            RED2(2, 1, s, bx) = make_ulonglong2(aU[a][2], aU[a][3]);
        }
        __syncthreads();

        // ---- epilogue: thread (eb, eu, elay) ----
        if (elay == 0) {
            if (iter < TSEQ) {
                float z0 = 0.f, z1 = 0.f, z2 = 0.f, z3 = 0.f, t0, t1;
#pragma unroll
                for (int s2 = 0; s2 < 8; ++s2) {
                    ulonglong2 v = RED2(0, eu, s2, eb);
                    upk(v.x, t0, t1); z0 += t0; z1 += t1;
                    upk(v.y, t0, t1); z2 += t0; z3 += t1;
                }
                float ig = sigmoidf(z0 + EB[0]);
                float fg = sigmoidf(z1 + EB[1]);
                float gv = fmaxf(z2 + EB[2], 0.f);
                float og = sigmoidf(z3 + EB[3]);
                ec = fg * ec + ig * gv;
                __stcg(&d_h1[wp * HB + (u0 + eu) * BATCH + eb],
                       og * fmaxf(ec, 0.f));
            }
        } else {
            if (iter >= 1) {
                float z0 = 0.f, z1 = 0.f, z2 = 0.f, z3 = 0.f, t0, t1;
#pragma unroll
                for (int s2 = 0; s2 < 8; ++s2) {
                    ulonglong2 v = RED2(1, eu, s2, eb);
                    upk(v.x, t0, t1); z0 += t0; z1 += t1;
                    upk(v.y, t0, t1); z2 += t0; z3 += t1;
                    v = RED2(2, eu, s2, eb);
                    upk(v.x, t0, t1); z0 += t0; z1 += t1;
                    upk(v.y, t0, t1); z2 += t0; z3 += t1;
                }
                float ig = sigmoidf(z0 + EB[0]);
                float fg = sigmoidf(z1 + EB[1]);
                float gv = fmaxf(z2 + EB[2], 0.f);
                float og = sigmoidf(z3 + EB[3]);
                ec = fg * ec + ig * gv;
                __stcg(&d_h2[wp * HB + (u0 + eu) * BATCH + eb],
                       og * fmaxf(ec, 0.f));
            }
        }
        __syncthreads();   // h stores + RED consumption complete

        // ---- grid barrier: EVERY iteration (final one protects dense reads) ----
        if (tid == 0) {
            asm volatile("red.release.gpu.global.add.s32 [%0], 1;"
                         :: "l"(&g_cnt) : "memory");
        }
        // x-part for the next step in the barrier shadow
        if (iter < TSEQ) {
            const int tn = (iter + 1 < TSEQ) ? (iter + 1) : (TSEQ - 1);
            compute_x(d_xT + (size_t)tn * (DIN * BATCH) + kx * BATCH + bb,
                      sW1, kx, xacc);
        }
        if (tid < 32) {
            const int tgt = NCTA * (iter + 1);
            int v;
            do {
                asm volatile("ld.acquire.gpu.global.s32 %0, [%1];"
                             : "=r"(v) : "l"(&g_cnt));
            } while (v < tgt);
        }
        __syncthreads();
    }

    // ---------------- Dense + softmax (CTA = one batch row) ----------------
    {
        const int brow = blockIdx.x;
        float* shh = (float*)red;          // [256] h
        float* rb  = shh + 256;            // [16] warp partials

        if (tid < 256)
            shh[tid] = __ldcg(&d_h2[HB + tid * BATCH + brow]);
        __syncthreads();

        const int o0 = tid, o1 = tid + 512;
        float acc0 = (o0 < DOUT) ? bd[o0] : -1e30f;
        float acc1 = (o1 < DOUT) ? bd[o1] : -1e30f;
#pragma unroll 8
        for (int k = 0; k < HID; ++k) {
            float h = shh[k];
            const float* wrow = Wd + (size_t)k * DOUT;
            if (o0 < DOUT) acc0 += h * wrow[o0];
            if (o1 < DOUT) acc1 += h * wrow[o1];
        }
        float lmax = fmaxf(acc0, acc1);
#pragma unroll
        for (int off = 16; off; off >>= 1)
            lmax = fmaxf(lmax, __shfl_xor_sync(0xffffffffu, lmax, off));
        if ((tid & 31) == 0) rb[tid >> 5] = lmax;
        __syncthreads();
        if (tid == 0) {
            float m = rb[0];
#pragma unroll
            for (int i = 1; i < 16; ++i) m = fmaxf(m, rb[i]);
            rb[0] = m;
        }
        __syncthreads();
        const float M = rb[0];
        __syncthreads();

        float e0 = (o0 < DOUT) ? __expf(acc0 - M) : 0.f;
        float e1 = (o1 < DOUT) ? __expf(acc1 - M) : 0.f;
        float lsum = e0 + e1;
#pragma unroll
        for (int off = 16; off; off >>= 1)
            lsum += __shfl_xor_sync(0xffffffffu, lsum, off);
        if ((tid & 31) == 0) rb[tid >> 5] = lsum;
        __syncthreads();
        if (tid == 0) {
            float sm = 0.f;
#pragma unroll
            for (int i = 0; i < 16; ++i) sm += rb[i];
            rb[0] = sm;
        }
        __syncthreads();
        const float inv = __fdividef(1.0f, rb[0]);
        if (o0 < DOUT) out[(size_t)brow * DOUT + o0] = e0 * inv;
        if (o1 < DOUT) out[(size_t)brow * DOUT + o1] = e1 * inv;
    }
}

// ---------------------------------------------------------------------------
static const int SMEM_BYTES = (256 * 3 + 128) * 4 * 8 /*weights 28,672*/ +
                              3 * 2 * 8 * 128 * 16 /*red 98,304*/;  // 126,976

extern "C" void kernel_launch(void* const* d_in, const int* in_sizes, int n_in,
                              void* d_out, int out_size) {
    const float* x  = (const float*)d_in[0];
    const float* W1 = (const float*)d_in[1];
    const float* U1 = (const float*)d_in[2];
    const float* b1 = (const float*)d_in[3];
    const float* W2 = (const float*)d_in[4];
    const float* U2 = (const float*)d_in[5];
    const float* b2 = (const float*)d_in[6];
    const float* Wd = (const float*)d_in[7];
    const float* bd = (const float*)d_in[8];
    float* out = (float*)d_out;

    cudaFuncSetAttribute(lstm_persistent,
                         cudaFuncAttributeMaxDynamicSharedMemorySize,
                         SMEM_BYTES);

    transpose_x_kernel<<<dim3(TSEQ, 4), 256>>>(x);
    lstm_persistent<<<NCTA, 512, SMEM_BYTES>>>(W1, U1, b1, W2, U2, b2,
                                               Wd, bd, out);
}